// round 10
// baseline (speedup 1.0000x reference)
#include <cuda_runtime.h>
#include <cuda_fp16.h>
#include <cstdint>

#define SEQ 2048
#define HD  64
#define BM  128
#define BN  64
#define NT  128
#define NTILES (SEQ / BN)
#define BH  32
#define PSC 0.125f
#define QJL 0.01f
#define QSCALE 0.18033688011112042f   // (1/8) * log2(e)

// smem: per tile-buffer, K = 128 chunks x 80B, V = 128 chunks x 80B
#define CH_SM 80
#define KREG_B (128 * CH_SM)           // 10240
#define BUF_B  (2 * KREG_B)            // 20480
#define SMEM_BYTES (2 * BUF_B)         // 40960  (Q staging uses 32KB of this)

// 16 MB scratch: dequantized fp16 K,V in fragment-chunked layout.
// chunk id (per bh,tile) = kc2*32 + g*4 + t ; 64B per chunk in gmem.
// K chunk payload: [nt(8)][pair(2)] half2 = {K[nt*8+g][kc2*16+2t+pair*8 + {0,1}]}
// V chunk payload: [dt(8)][pair(2)] half2 = {V[kc2*16+2t+pair*8 + {0,1}][dt*8+g]}
__device__ __half2 g_kd2[BH * SEQ * HD / 2];
__device__ __half2 g_vd2[BH * SEQ * HD / 2];

__device__ __forceinline__ float ex2f_(float x) {
    float r; asm("ex2.approx.f32 %0, %1;" : "=f"(r) : "f"(x)); return r;
}
__device__ __forceinline__ uint32_t h2u(__half2 h) { return *reinterpret_cast<uint32_t*>(&h); }

__device__ __forceinline__ void mma_f16(float* d, const uint32_t* a,
                                        uint32_t b0, uint32_t b1) {
    asm volatile(
        "mma.sync.aligned.m16n8k16.row.col.f32.f16.f16.f32 "
        "{%0,%1,%2,%3}, {%4,%5,%6,%7}, {%8,%9}, {%0,%1,%2,%3};"
        : "+f"(d[0]), "+f"(d[1]), "+f"(d[2]), "+f"(d[3])
        : "r"(a[0]), "r"(a[1]), "r"(a[2]), "r"(a[3]), "r"(b0), "r"(b1));
}
__device__ __forceinline__ uint32_t smem_u32(const void* p) {
    uint32_t a;
    asm("{ .reg .u64 t; cvta.to.shared.u64 t, %1; cvt.u32.u64 %0, t; }" : "=r"(a) : "l"(p));
    return a;
}
__device__ __forceinline__ void cp16(uint32_t dst, const void* src) {
    asm volatile("cp.async.cg.shared.global [%0], [%1], 16;" :: "r"(dst), "l"(src));
}

// ---- fused pre-pass (unchanged from R9) ----
#define KSTR2 36
#define VSTRH 72

__global__ void __launch_bounds__(256) deq_kv(
    const float* __restrict__ kp, const float* __restrict__ kq,
    const float* __restrict__ vp, const float* __restrict__ vq)
{
    __shared__ __half2 sK2[64 * KSTR2];
    __shared__ __half  sVt[64 * VSTRH];

    const int tid = threadIdx.x;
    const size_t rowbase = (size_t)blockIdx.x * (64 * HD);

    #pragma unroll
    for (int it = 0; it < 4; ++it) {
        int idx = tid + it * 256;
        int r = idx >> 4, c4 = idx & 15;
        size_t gq = rowbase + (size_t)r * HD + c4 * 4;

        float4 a = *reinterpret_cast<const float4*>(kp + gq);
        float4 b = *reinterpret_cast<const float4*>(kq + gq);
        __half2 h0 = __floats2half2_rn(a.x * PSC + b.x * QJL, a.y * PSC + b.y * QJL);
        __half2 h1 = __floats2half2_rn(a.z * PSC + b.z * QJL, a.w * PSC + b.w * QJL);
        *reinterpret_cast<uint2*>(&sK2[r * KSTR2 + c4 * 2]) =
            make_uint2(h2u(h0), h2u(h1));

        a = *reinterpret_cast<const float4*>(vp + gq);
        b = *reinterpret_cast<const float4*>(vq + gq);
        sVt[(c4 * 4 + 0) * VSTRH + r] = __float2half_rn(a.x * PSC + b.x * QJL);
        sVt[(c4 * 4 + 1) * VSTRH + r] = __float2half_rn(a.y * PSC + b.y * QJL);
        sVt[(c4 * 4 + 2) * VSTRH + r] = __float2half_rn(a.z * PSC + b.z * QJL);
        sVt[(c4 * 4 + 3) * VSTRH + r] = __float2half_rn(a.w * PSC + b.w * QJL);
    }
    __syncthreads();

    const int c   = tid & 127;
    const int t   = c & 3;
    const int g   = (c >> 2) & 7;
    const int kc2 = c >> 5;

    uint32_t w[16];
    char* dst;
    if (tid < 128) {
        #pragma unroll
        for (int nt = 0; nt < 8; ++nt) {
            int rw = (nt * 8 + g) * KSTR2 + kc2 * 8 + t;
            w[2 * nt]     = h2u(sK2[rw]);
            w[2 * nt + 1] = h2u(sK2[rw + 4]);
        }
        dst = reinterpret_cast<char*>(g_kd2) + (size_t)blockIdx.x * 8192 + c * 64;
    } else {
        #pragma unroll
        for (int dt = 0; dt < 8; ++dt) {
            int n = dt * 8 + g;
            int a0 = n * VSTRH + kc2 * 16 + 2 * t;
            w[2 * dt]     = *reinterpret_cast<uint32_t*>(&sVt[a0]);
            w[2 * dt + 1] = *reinterpret_cast<uint32_t*>(&sVt[a0 + 8]);
        }
        dst = reinterpret_cast<char*>(g_vd2) + (size_t)blockIdx.x * 8192 + c * 64;
    }
    #pragma unroll
    for (int u4 = 0; u4 < 4; ++u4)
        *reinterpret_cast<uint4*>(dst + u4 * 16) =
            make_uint4(w[4 * u4], w[4 * u4 + 1], w[4 * u4 + 2], w[4 * u4 + 3]);
}

// ---- attention: BM=128, each warp owns 32 Q rows (2 m-fragments) ----
__global__ void __launch_bounds__(NT, 2) tq_attn_mma(
    const float* __restrict__ q, float* __restrict__ out)
{
    extern __shared__ char dsm[];
    const uint32_t sb = smem_u32(dsm);

    const int tid  = threadIdx.x;
    const int wid  = tid >> 5;
    const int lane = tid & 31;
    const int g    = lane >> 2;
    const int t    = lane & 3;
    const int wrow = wid * 32;     // warp's first Q row (owns 32 rows)

    const int    m0   = blockIdx.x * BM;
    const int    bh   = blockIdx.y;
    const size_t base = (size_t)bh * (size_t)(SEQ * HD);

    // ---- stage Q (128 rows x 64 fp32 = 32KB) in buffer region ----
    {
        float* sQ = reinterpret_cast<float*>(dsm);
        #pragma unroll
        for (int it = 0; it < 16; ++it) {
            int idx = tid + it * NT;          // 0..2047
            int r = idx >> 4, c4 = idx & 15;
            float4 v = *reinterpret_cast<const float4*>(
                q + base + (size_t)(m0 + r) * HD + c4 * 4);
            *reinterpret_cast<float4*>(&sQ[r * HD + c4 * 4]) = v;
        }
    }
    __syncthreads();
    uint32_t qa[2][4][4];
    #pragma unroll
    for (int mf = 0; mf < 2; ++mf) {
        const float* q0 = reinterpret_cast<float*>(dsm) + (wrow + mf * 16 + g) * HD + 2 * t;
        const float* q8 = q0 + 8 * HD;
        #pragma unroll
        for (int kc2 = 0; kc2 < 4; ++kc2) {
            int c = kc2 * 16;
            qa[mf][kc2][0] = h2u(__floats2half2_rn(QSCALE * q0[c],     QSCALE * q0[c + 1]));
            qa[mf][kc2][1] = h2u(__floats2half2_rn(QSCALE * q8[c],     QSCALE * q8[c + 1]));
            qa[mf][kc2][2] = h2u(__floats2half2_rn(QSCALE * q0[c + 8], QSCALE * q0[c + 9]));
            qa[mf][kc2][3] = h2u(__floats2half2_rn(QSCALE * q8[c + 8], QSCALE * q8[c + 9]));
        }
    }
    __syncthreads();

    const char* kgm = reinterpret_cast<const char*>(g_kd2) + (size_t)bh * 32 * 8192;
    const char* vgm = reinterpret_cast<const char*>(g_vd2) + (size_t)bh * 32 * 8192;

    // ---- prologue: async-load tile 0 ----
    #pragma unroll
    for (int it = 0; it < 4; ++it) {
        int part = tid + it * NT;
        uint32_t doff = (part >> 2) * CH_SM + (part & 3) * 16;
        cp16(sb + doff, kgm + part * 16);
        cp16(sb + KREG_B + doff, vgm + part * 16);
    }
    asm volatile("cp.async.commit_group;" ::: "memory");

    float o[2][8][4];
    #pragma unroll
    for (int mf = 0; mf < 2; ++mf)
        #pragma unroll
        for (int i = 0; i < 8; ++i)
            #pragma unroll
            for (int j = 0; j < 4; ++j) o[mf][i][j] = 0.f;
    float rs[2][2] = {{0.f, 0.f}, {0.f, 0.f}};

    const uint32_t mych = (g * 4 + t) * CH_SM;

    for (int tl = 0; tl < NTILES; ++tl) {
        if (tl + 1 < NTILES) {
            const uint32_t nb = sb + ((tl + 1) & 1) * BUF_B;
            const char* ks = kgm + (size_t)(tl + 1) * 8192;
            const char* vs = vgm + (size_t)(tl + 1) * 8192;
            #pragma unroll
            for (int it = 0; it < 4; ++it) {
                int part = tid + it * NT;
                uint32_t doff = (part >> 2) * CH_SM + (part & 3) * 16;
                cp16(nb + doff, ks + part * 16);
                cp16(nb + KREG_B + doff, vs + part * 16);
            }
            asm volatile("cp.async.commit_group;" ::: "memory");
            asm volatile("cp.async.wait_group 1;" ::: "memory");
        } else {
            asm volatile("cp.async.wait_group 0;" ::: "memory");
        }
        __syncthreads();

        // ---- S = Q K^T : each B-fragment load feeds BOTH m-fragments ----
        float s[2][8][4];
        #pragma unroll
        for (int mf = 0; mf < 2; ++mf)
            #pragma unroll
            for (int i = 0; i < 8; ++i)
                #pragma unroll
                for (int j = 0; j < 4; ++j) s[mf][i][j] = 0.f;

        #pragma unroll
        for (int kc2 = 0; kc2 < 4; ++kc2) {
            const char* ca = dsm + (tl & 1) * BUF_B + kc2 * 32 * CH_SM + mych;
            uint4 B0 = *reinterpret_cast<const uint4*>(ca);
            uint4 B1 = *reinterpret_cast<const uint4*>(ca + 16);
            uint4 B2 = *reinterpret_cast<const uint4*>(ca + 32);
            uint4 B3 = *reinterpret_cast<const uint4*>(ca + 48);
            #pragma unroll
            for (int mf = 0; mf < 2; ++mf) {
                mma_f16(s[mf][0], qa[mf][kc2], B0.x, B0.y);
                mma_f16(s[mf][1], qa[mf][kc2], B0.z, B0.w);
                mma_f16(s[mf][2], qa[mf][kc2], B1.x, B1.y);
                mma_f16(s[mf][3], qa[mf][kc2], B1.z, B1.w);
                mma_f16(s[mf][4], qa[mf][kc2], B2.x, B2.y);
                mma_f16(s[mf][5], qa[mf][kc2], B2.z, B2.w);
                mma_f16(s[mf][6], qa[mf][kc2], B3.x, B3.y);
                mma_f16(s[mf][7], qa[mf][kc2], B3.z, B3.w);
            }
        }

        // ---- fused softmax + PV per k-chunk (s consumed in place) ----
        #pragma unroll
        for (int kc2 = 0; kc2 < 4; ++kc2) {
            uint32_t pa[2][4];
            #pragma unroll
            for (int mf = 0; mf < 2; ++mf) {
                float p00 = ex2f_(s[mf][2 * kc2][0]);
                float p01 = ex2f_(s[mf][2 * kc2][1]);
                float p02 = ex2f_(s[mf][2 * kc2][2]);
                float p03 = ex2f_(s[mf][2 * kc2][3]);
                float p10 = ex2f_(s[mf][2 * kc2 + 1][0]);
                float p11 = ex2f_(s[mf][2 * kc2 + 1][1]);
                float p12 = ex2f_(s[mf][2 * kc2 + 1][2]);
                float p13 = ex2f_(s[mf][2 * kc2 + 1][3]);
                rs[mf][0] += (p00 + p01) + (p10 + p11);
                rs[mf][1] += (p02 + p03) + (p12 + p13);
                pa[mf][0] = h2u(__floats2half2_rn(p00, p01));
                pa[mf][1] = h2u(__floats2half2_rn(p02, p03));
                pa[mf][2] = h2u(__floats2half2_rn(p10, p11));
                pa[mf][3] = h2u(__floats2half2_rn(p12, p13));
            }
            const char* cv = dsm + (tl & 1) * BUF_B + KREG_B + kc2 * 32 * CH_SM + mych;
            uint4 B0 = *reinterpret_cast<const uint4*>(cv);
            uint4 B1 = *reinterpret_cast<const uint4*>(cv + 16);
            uint4 B2 = *reinterpret_cast<const uint4*>(cv + 32);
            uint4 B3 = *reinterpret_cast<const uint4*>(cv + 48);
            #pragma unroll
            for (int mf = 0; mf < 2; ++mf) {
                mma_f16(o[mf][0], pa[mf], B0.x, B0.y);
                mma_f16(o[mf][1], pa[mf], B0.z, B0.w);
                mma_f16(o[mf][2], pa[mf], B1.x, B1.y);
                mma_f16(o[mf][3], pa[mf], B1.z, B1.w);
                mma_f16(o[mf][4], pa[mf], B2.x, B2.y);
                mma_f16(o[mf][5], pa[mf], B2.z, B2.w);
                mma_f16(o[mf][6], pa[mf], B3.x, B3.y);
                mma_f16(o[mf][7], pa[mf], B3.z, B3.w);
            }
        }
        __syncthreads();
    }

    // ---- epilogue ----
    #pragma unroll
    for (int mf = 0; mf < 2; ++mf) {
        float r0s = rs[mf][0], r1s = rs[mf][1];
        r0s += __shfl_xor_sync(0xffffffffu, r0s, 1);
        r0s += __shfl_xor_sync(0xffffffffu, r0s, 2);
        r1s += __shfl_xor_sync(0xffffffffu, r1s, 1);
        r1s += __shfl_xor_sync(0xffffffffu, r1s, 2);
        const float inv0 = 1.0f / r0s;
        const float inv1 = 1.0f / r1s;

        const size_t row0 = base + (size_t)(m0 + wrow + mf * 16 + g) * HD;
        const size_t row1 = row0 + 8 * HD;
        #pragma unroll
        for (int dt = 0; dt < 8; ++dt) {
            float2 w0 = make_float2(o[mf][dt][0] * inv0, o[mf][dt][1] * inv0);
            float2 w1 = make_float2(o[mf][dt][2] * inv1, o[mf][dt][3] * inv1);
            *reinterpret_cast<float2*>(out + row0 + dt * 8 + 2 * t) = w0;
            *reinterpret_cast<float2*>(out + row1 + dt * 8 + 2 * t) = w1;
        }
    }
}

extern "C" void kernel_launch(void* const* d_in, const int* in_sizes, int n_in,
                              void* d_out, int out_size)
{
    const float* q  = (const float*)d_in[0];
    const float* kp = (const float*)d_in[1];
    const float* kq = (const float*)d_in[2];
    const float* vp = (const float*)d_in[3];
    const float* vq = (const float*)d_in[4];
    float* out = (float*)d_out;

    static int cfg_done = 0;
    if (!cfg_done) {
        cudaFuncSetAttribute(tq_attn_mma,
                             cudaFuncAttributeMaxDynamicSharedMemorySize, SMEM_BYTES);
        cfg_done = 1;
    }

    deq_kv<<<BH * NTILES, 256>>>(kp, kq, vp, vq);

    dim3 grid(SEQ / BM, BH);
    tq_attn_mma<<<grid, NT, SMEM_BYTES>>>(q, out);
}